// round 4
// baseline (speedup 1.0000x reference)
#include <cuda_runtime.h>

#define BB 64
#define TT 200
#define NS 1000

// ---------------- device scratch ----------------
__device__ float2 g_Wsk[1000 * 32];   // (w[l], w[l+32]) per skill, softmaxed
__device__ float2 g_EA [2000 * 64];   // (e, a) per x-index, per d
__device__ float2 g_G  [1000 * 32];   // (g[l], g[l+32]) = k·fW2^T + fb
__device__ int    g_idx[BB * TT];     // skill | (x << 16)
__device__ float  g_read[BB * TT * 64];

static __device__ __forceinline__ float tanh_a(float x) {
    float y; asm("tanh.approx.f32 %0, %1;" : "=f"(y) : "f"(x)); return y;
}
static __device__ __forceinline__ float sigmoid_e(float x) {
    return 1.0f / (1.0f + __expf(-x));
}

// =====================================================================
// Kernel P: precompute tables. 1 row per warp.
//   blocks [0,125):   skill rows: Wsk[s]=softmax(k_emb[s]·Mk^T), G[s]=k_emb[s]·fW2^T+fb
//   blocks [125,375): x rows:     EA[j]=(sigmoid(v·eW^T+eb), tanh(v·aW^T+ab))
// =====================================================================
__global__ __launch_bounds__(256) void k_pre(
    const int* __restrict__ skills, const int* __restrict__ responses,
    const float* __restrict__ k_emb, const float* __restrict__ v_emb,
    const float* __restrict__ Mk, const float* __restrict__ fW,
    const float* __restrict__ fb, const float* __restrict__ eW,
    const float* __restrict__ eb, const float* __restrict__ aW,
    const float* __restrict__ ab)
{
    __shared__ __align__(16) float W0[64 * 68];
    __shared__ __align__(16) float W1[64 * 68];

    int tid = threadIdx.x;
    int gt = blockIdx.x * 256 + tid;
    if (gt < BB * TT) {
        int s = skills[gt], r = responses[gt];
        int mr = (r > -1) ? r : 0;
        g_idx[gt] = s | ((s + NS * mr) << 16);
    }

    bool isA = blockIdx.x < 125;
    {
        const float4* s0 = isA ? (const float4*)Mk : (const float4*)eW;
        const float4* s1f = (const float4*)fW;
        const float4* s1a = (const float4*)aW;
#pragma unroll
        for (int k = 0; k < 4; k++) {
            int i = tid + k * 256;                 // float4 index, 0..1023
            int o = i >> 4, q4 = i & 15;
            float4 v0 = s0[i];
            float4 v1 = isA ? s1f[o * 32 + 16 + q4] : s1a[i];
            *(float4*)&W0[o * 68 + q4 * 4] = v0;
            *(float4*)&W1[o * 68 + q4 * 4] = v1;
        }
    }
    __syncthreads();

    int w = tid >> 5, l = tid & 31;
    const float4* pL0 = (const float4*)&W0[l * 68];
    const float4* pH0 = (const float4*)&W0[(l + 32) * 68];
    const float4* pL1 = (const float4*)&W1[l * 68];
    const float4* pH1 = (const float4*)&W1[(l + 32) * 68];
    // row stride 68 floats = 17 float4
#define WROW 17

    if (isA) {
        int r0 = blockIdx.x * 8 + w;             // [0,1000)
        const float4* xk = (const float4*)&k_emb[r0 * 64];

        float mlA = 0.f, mhA = 0.f, glA = 0.f, ghA = 0.f;
        float mlB = 0.f, mhB = 0.f, glB = 0.f, ghB = 0.f;
#pragma unroll
        for (int q = 0; q < 16; q += 2) {
            float4 xa = xk[q];
            float4 xb = xk[q + 1];
            float4 aL = pL0[0]; float4 aL2 = pL0[1]; pL0 += 2;
            float4 aH = pH0[0]; float4 aH2 = pH0[1]; pH0 += 2;
            float4 bL = pL1[0]; float4 bL2 = pL1[1]; pL1 += 2;
            float4 bH = pH1[0]; float4 bH2 = pH1[1]; pH1 += 2;
            mlA = fmaf(xa.x, aL.x, mlA); mlA = fmaf(xa.y, aL.y, mlA);
            mlA = fmaf(xa.z, aL.z, mlA); mlA = fmaf(xa.w, aL.w, mlA);
            mhA = fmaf(xa.x, aH.x, mhA); mhA = fmaf(xa.y, aH.y, mhA);
            mhA = fmaf(xa.z, aH.z, mhA); mhA = fmaf(xa.w, aH.w, mhA);
            glA = fmaf(xa.x, bL.x, glA); glA = fmaf(xa.y, bL.y, glA);
            glA = fmaf(xa.z, bL.z, glA); glA = fmaf(xa.w, bL.w, glA);
            ghA = fmaf(xa.x, bH.x, ghA); ghA = fmaf(xa.y, bH.y, ghA);
            ghA = fmaf(xa.z, bH.z, ghA); ghA = fmaf(xa.w, bH.w, ghA);
            mlB = fmaf(xb.x, aL2.x, mlB); mlB = fmaf(xb.y, aL2.y, mlB);
            mlB = fmaf(xb.z, aL2.z, mlB); mlB = fmaf(xb.w, aL2.w, mlB);
            mhB = fmaf(xb.x, aH2.x, mhB); mhB = fmaf(xb.y, aH2.y, mhB);
            mhB = fmaf(xb.z, aH2.z, mhB); mhB = fmaf(xb.w, aH2.w, mhB);
            glB = fmaf(xb.x, bL2.x, glB); glB = fmaf(xb.y, bL2.y, glB);
            glB = fmaf(xb.z, bL2.z, glB); glB = fmaf(xb.w, bL2.w, glB);
            ghB = fmaf(xb.x, bH2.x, ghB); ghB = fmaf(xb.y, bH2.y, ghB);
            ghB = fmaf(xb.z, bH2.z, ghB); ghB = fmaf(xb.w, bH2.w, ghB);
        }
        float ml = mlA + mlB, mh = mhA + mhB;
        float gl = glA + glB, gh = ghA + ghB;

        // softmax (logits tiny; skip max-subtraction)
        float e0 = __expf(ml), e1 = __expf(mh);
        float s = e0 + e1;
#pragma unroll
        for (int o = 16; o; o >>= 1) s += __shfl_xor_sync(~0u, s, o);
        float inv = 1.0f / s;
        g_Wsk[r0 * 32 + l] = make_float2(e0 * inv, e1 * inv);
        g_G[r0 * 32 + l]   = make_float2(gl + fb[l], gh + fb[l + 32]);
    } else {
        int j0 = (blockIdx.x - 125) * 8 + w;     // [0,2000)
        const float4* xv = (const float4*)&v_emb[j0 * 64];

        float elA = 0.f, ehA = 0.f, alA = 0.f, ahA = 0.f;
        float elB = 0.f, ehB = 0.f, alB = 0.f, ahB = 0.f;
#pragma unroll
        for (int q = 0; q < 16; q += 2) {
            float4 xa = xv[q];
            float4 xb = xv[q + 1];
            float4 aL = pL0[0]; float4 aL2 = pL0[1]; pL0 += 2;
            float4 aH = pH0[0]; float4 aH2 = pH0[1]; pH0 += 2;
            float4 bL = pL1[0]; float4 bL2 = pL1[1]; pL1 += 2;
            float4 bH = pH1[0]; float4 bH2 = pH1[1]; pH1 += 2;
            elA = fmaf(xa.x, aL.x, elA); elA = fmaf(xa.y, aL.y, elA);
            elA = fmaf(xa.z, aL.z, elA); elA = fmaf(xa.w, aL.w, elA);
            ehA = fmaf(xa.x, aH.x, ehA); ehA = fmaf(xa.y, aH.y, ehA);
            ehA = fmaf(xa.z, aH.z, ehA); ehA = fmaf(xa.w, aH.w, ehA);
            alA = fmaf(xa.x, bL.x, alA); alA = fmaf(xa.y, bL.y, alA);
            alA = fmaf(xa.z, bL.z, alA); alA = fmaf(xa.w, bL.w, alA);
            ahA = fmaf(xa.x, bH.x, ahA); ahA = fmaf(xa.y, bH.y, ahA);
            ahA = fmaf(xa.z, bH.z, ahA); ahA = fmaf(xa.w, bH.w, ahA);
            elB = fmaf(xb.x, aL2.x, elB); elB = fmaf(xb.y, aL2.y, elB);
            elB = fmaf(xb.z, aL2.z, elB); elB = fmaf(xb.w, aL2.w, elB);
            ehB = fmaf(xb.x, aH2.x, ehB); ehB = fmaf(xb.y, aH2.y, ehB);
            ehB = fmaf(xb.z, aH2.z, ehB); ehB = fmaf(xb.w, aH2.w, ehB);
            alB = fmaf(xb.x, bL2.x, alB); alB = fmaf(xb.y, bL2.y, alB);
            alB = fmaf(xb.z, bL2.z, alB); alB = fmaf(xb.w, bL2.w, alB);
            ahB = fmaf(xb.x, bH2.x, ahB); ahB = fmaf(xb.y, bH2.y, ahB);
            ahB = fmaf(xb.z, bH2.z, ahB); ahB = fmaf(xb.w, bH2.w, ahB);
        }
        float el = elA + elB, eh = ehA + ehB;
        float al = alA + alB, ah = ahA + ahB;
        g_EA[j0 * 64 + l]      = make_float2(sigmoid_e(el + eb[l]),      tanhf(al + ab[l]));
        g_EA[j0 * 64 + l + 32] = make_float2(sigmoid_e(eh + eb[l + 32]), tanhf(ah + ab[l + 32]));
    }
}

// =====================================================================
// Kernel S: scan. warp = (b, d-pair); lane = m (m and m+32); 2048 warps.
// Block of 8 warps shares one batch b (L1 reuse of w rows).
// 16-step chunks, deferred transposed reduction in smem.
// =====================================================================
__global__ __launch_bounds__(256) void k_scan(const float* __restrict__ Mv0)
{
    __shared__ __align__(16) float buf[8][32][36];

    int w = threadIdx.x >> 5, l = threadIdx.x & 31;
    int wg = blockIdx.x * 8 + w;          // 0..2047
    int b  = wg >> 5;                     // 0..63 (all warps in block same b)
    int d0 = (wg & 31) << 1;              // even d

    float2 sa = *(const float2*)&Mv0[l * 64 + d0];        // (m=l,   d0/d1)
    float2 sb = *(const float2*)&Mv0[(l + 32) * 64 + d0]; // (m=l+32,d0/d1)

    const int* idxp = g_idx + b * TT;
    float* rd = g_read + b * TT * 64 + d0;
    float (*mybuf)[36] = buf[w];

    int jr = l >> 1, comp = l & 1;        // reduction assignment

    int pk = 0;
    for (int c = 0; c < 12; c++) {
        int t0 = c * 16;
        int lanebase = (c & 1) * 16;
        if (lanebase == 0) pk = idxp[t0 + l];   // covers 32 steps

        float2 w2b[8]; float4 eab[8];
#pragma unroll
        for (int j = 0; j < 8; j++) {
            int p = __shfl_sync(0xffffffffu, pk, lanebase + j);
            w2b[j] = g_Wsk[(p & 0xffff) * 32 + l];
            eab[j] = *(const float4*)&g_EA[(p >> 16) * 64 + d0];
        }
#pragma unroll
        for (int j = 0; j < 16; j++) {
            float2 w2 = w2b[j & 7];
            float4 ea = eab[j & 7];
            if (j < 8) {
                int p = __shfl_sync(0xffffffffu, pk, lanebase + j + 8);
                w2b[j & 7] = g_Wsk[(p & 0xffff) * 32 + l];
                eab[j & 7] = *(const float4*)&g_EA[(p >> 16) * 64 + d0];
            }
            float r0 = w2.x * sa.x + w2.y * sb.x;   // read BEFORE update
            float r1 = w2.x * sa.y + w2.y * sb.y;
            sa.x = fmaf(w2.x, fmaf(-ea.x, sa.x, ea.y), sa.x);
            sb.x = fmaf(w2.y, fmaf(-ea.x, sb.x, ea.y), sb.x);
            sa.y = fmaf(w2.x, fmaf(-ea.z, sa.y, ea.w), sa.y);
            sb.y = fmaf(w2.y, fmaf(-ea.z, sb.y, ea.w), sb.y);
            mybuf[2 * j][l]     = r0;
            mybuf[2 * j + 1][l] = r1;
        }
        __syncwarp();
        const float4* rowp = (const float4*)&mybuf[l][0];
        float sum = 0.f;
#pragma unroll
        for (int k = 0; k < 8; k++) {
            float4 v = rowp[k];
            sum += (v.x + v.y) + (v.z + v.w);
        }
        rd[(t0 + jr) * 64 + comp] = sum;
        __syncwarp();
    }
    // tail: t = 192..199
    {
        pk = (l < 8) ? idxp[192 + l] : 0;
        float2 w2b[8]; float4 eab[8];
#pragma unroll
        for (int j = 0; j < 8; j++) {
            int p = __shfl_sync(0xffffffffu, pk, j);
            w2b[j] = g_Wsk[(p & 0xffff) * 32 + l];
            eab[j] = *(const float4*)&g_EA[(p >> 16) * 64 + d0];
        }
#pragma unroll
        for (int j = 0; j < 8; j++) {
            float2 w2 = w2b[j];
            float4 ea = eab[j];
            float r0 = w2.x * sa.x + w2.y * sb.x;
            float r1 = w2.x * sa.y + w2.y * sb.y;
            sa.x = fmaf(w2.x, fmaf(-ea.x, sa.x, ea.y), sa.x);
            sb.x = fmaf(w2.y, fmaf(-ea.x, sb.x, ea.y), sb.x);
            sa.y = fmaf(w2.x, fmaf(-ea.z, sa.y, ea.w), sa.y);
            sb.y = fmaf(w2.y, fmaf(-ea.z, sb.y, ea.w), sb.y);
            mybuf[2 * j][l]     = r0;
            mybuf[2 * j + 1][l] = r1;
        }
        __syncwarp();
        if (l < 16) {
            const float4* rowp = (const float4*)&mybuf[l][0];
            float sum = 0.f;
#pragma unroll
            for (int k = 0; k < 8; k++) {
                float4 v = rowp[k];
                sum += (v.x + v.y) + (v.z + v.w);
            }
            rd[(192 + jr) * 64 + comp] = sum;
        }
    }
}

// =====================================================================
// Kernel O: p = sigmoid( tanh(read·fW1^T + G[skill]) · pW^T + pb )
// 32 rows/block; 398 blocks (12736 rows exactly)
// =====================================================================
__global__ __launch_bounds__(256) void k_out(
    const float* __restrict__ fW, const float* __restrict__ pW,
    const float* __restrict__ pb, float* __restrict__ out)
{
    __shared__ __align__(16) float F1[64 * 68];

    int tid = threadIdx.x;
    {
        const float4* src = (const float4*)fW;
#pragma unroll
        for (int k = 0; k < 4; k++) {
            int i = tid + k * 256;
            int o = i >> 4, q4 = i & 15;
            *(float4*)&F1[o * 68 + q4 * 4] = src[o * 32 + q4];
        }
    }
    __syncthreads();

    int w = tid >> 5, l = tid & 31;
    const float4* pL = (const float4*)&F1[l * 68];
    const float4* pH = (const float4*)&F1[(l + 32) * 68];
    float pl = pW[l], ph = pW[l + 32];
    float pbv = pb[0];

    for (int rp = 0; rp < 2; rp++) {
        int row0 = blockIdx.x * 32 + w * 4 + rp * 2;
        int row1 = row0 + 1;
        int b0 = row0 / 199, t0 = row0 - b0 * 199 + 1;
        int b1 = row1 / 199, t1 = row1 - b1 * 199 + 1;
        int i0 = b0 * TT + t0, i1 = b1 * TT + t1;

        const float4* X0 = (const float4*)&g_read[i0 * 64];
        const float4* X1 = (const float4*)&g_read[i1 * 64];

        float a00 = 0.f, a01 = 0.f, a10 = 0.f, a11 = 0.f;
#pragma unroll
        for (int q = 0; q < 16; q++) {
            float4 xa = X0[q];
            float4 xb = X1[q];
            float4 mL = pL[q];
            float4 mH = pH[q];
            a00 = fmaf(xa.x, mL.x, a00); a00 = fmaf(xa.y, mL.y, a00);
            a00 = fmaf(xa.z, mL.z, a00); a00 = fmaf(xa.w, mL.w, a00);
            a01 = fmaf(xa.x, mH.x, a01); a01 = fmaf(xa.y, mH.y, a01);
            a01 = fmaf(xa.z, mH.z, a01); a01 = fmaf(xa.w, mH.w, a01);
            a10 = fmaf(xb.x, mL.x, a10); a10 = fmaf(xb.y, mL.y, a10);
            a10 = fmaf(xb.z, mL.z, a10); a10 = fmaf(xb.w, mL.w, a10);
            a11 = fmaf(xb.x, mH.x, a11); a11 = fmaf(xb.y, mH.y, a11);
            a11 = fmaf(xb.z, mH.z, a11); a11 = fmaf(xb.w, mH.w, a11);
        }

        int sk0 = g_idx[i0] & 0xffff;
        int sk1 = g_idx[i1] & 0xffff;
        float2 G0 = g_G[sk0 * 32 + l];
        float2 G1 = g_G[sk1 * 32 + l];

        float f00 = tanh_a(a00 + G0.x), f01 = tanh_a(a01 + G0.y);
        float f10 = tanh_a(a10 + G1.x), f11 = tanh_a(a11 + G1.y);

        float r0 = f00 * pl + f01 * ph;
        float r1 = f10 * pl + f11 * ph;
#pragma unroll
        for (int o = 16; o; o >>= 1) {
            r0 += __shfl_xor_sync(~0u, r0, o);
            r1 += __shfl_xor_sync(~0u, r1, o);
        }
        if (l == 0) {
            out[row0] = sigmoid_e(r0 + pbv);
            out[row1] = sigmoid_e(r1 + pbv);
        }
    }
}

// =====================================================================
// launch
// =====================================================================
extern "C" void kernel_launch(void* const* d_in, const int* in_sizes, int n_in,
                              void* d_out, int out_size) {
    const int*   skills    = (const int*)d_in[0];
    const int*   responses = (const int*)d_in[1];
    const float* k_emb     = (const float*)d_in[2];
    const float* v_emb     = (const float*)d_in[3];
    const float* Mk        = (const float*)d_in[4];
    const float* Mv0       = (const float*)d_in[5];
    const float* fW        = (const float*)d_in[6];
    const float* fb        = (const float*)d_in[7];
    const float* eW        = (const float*)d_in[8];
    const float* eb        = (const float*)d_in[9];
    const float* aW        = (const float*)d_in[10];
    const float* ab        = (const float*)d_in[11];
    const float* pW        = (const float*)d_in[12];
    const float* pb        = (const float*)d_in[13];
    float* out = (float*)d_out;

    k_pre <<<375, 256>>>(skills, responses, k_emb, v_emb, Mk, fW, fb, eW, eb, aW, ab);
    k_scan<<<256, 256>>>(Mv0);
    k_out <<<398, 256>>>(fW, pW, pb, out);
}

// round 5
// speedup vs baseline: 1.1273x; 1.1273x over previous
#include <cuda_runtime.h>

#define BB 64
#define TT 200
#define NS 1000

// ---------------- device scratch ----------------
__device__ float2 g_Wsk[1000 * 32];   // (w[l], w[l+32]) per skill, softmaxed
__device__ float2 g_EA [2000 * 64];   // (e, a) per x-index, per d
__device__ float2 g_G  [1000 * 32];   // (g[l], g[l+32]) = k·fW2^T + fb
__device__ int    g_idx[BB * TT];     // skill | (x << 16)
__device__ float  g_read[BB * TT * 64];

static __device__ __forceinline__ float tanh_a(float x) {
    float y; asm("tanh.approx.f32 %0, %1;" : "=f"(y) : "f"(x)); return y;
}
static __device__ __forceinline__ float sigmoid_e(float x) {
    return 1.0f / (1.0f + __expf(-x));
}

// =====================================================================
// Kernel P: precompute tables. 1 row per warp. (round-4 version, 9.6us)
// =====================================================================
__global__ __launch_bounds__(256) void k_pre(
    const int* __restrict__ skills, const int* __restrict__ responses,
    const float* __restrict__ k_emb, const float* __restrict__ v_emb,
    const float* __restrict__ Mk, const float* __restrict__ fW,
    const float* __restrict__ fb, const float* __restrict__ eW,
    const float* __restrict__ eb, const float* __restrict__ aW,
    const float* __restrict__ ab)
{
    __shared__ __align__(16) float W0[64 * 68];
    __shared__ __align__(16) float W1[64 * 68];

    int tid = threadIdx.x;
    int gt = blockIdx.x * 256 + tid;
    if (gt < BB * TT) {
        int s = skills[gt], r = responses[gt];
        int mr = (r > -1) ? r : 0;
        g_idx[gt] = s | ((s + NS * mr) << 16);
    }

    bool isA = blockIdx.x < 125;
    {
        const float4* s0 = isA ? (const float4*)Mk : (const float4*)eW;
        const float4* s1f = (const float4*)fW;
        const float4* s1a = (const float4*)aW;
#pragma unroll
        for (int k = 0; k < 4; k++) {
            int i = tid + k * 256;                 // float4 index, 0..1023
            int o = i >> 4, q4 = i & 15;
            float4 v0 = s0[i];
            float4 v1 = isA ? s1f[o * 32 + 16 + q4] : s1a[i];
            *(float4*)&W0[o * 68 + q4 * 4] = v0;
            *(float4*)&W1[o * 68 + q4 * 4] = v1;
        }
    }
    __syncthreads();

    int w = tid >> 5, l = tid & 31;
    const float4* pL0 = (const float4*)&W0[l * 68];
    const float4* pH0 = (const float4*)&W0[(l + 32) * 68];
    const float4* pL1 = (const float4*)&W1[l * 68];
    const float4* pH1 = (const float4*)&W1[(l + 32) * 68];

    if (isA) {
        int r0 = blockIdx.x * 8 + w;             // [0,1000)
        const float4* xk = (const float4*)&k_emb[r0 * 64];

        float mlA = 0.f, mhA = 0.f, glA = 0.f, ghA = 0.f;
        float mlB = 0.f, mhB = 0.f, glB = 0.f, ghB = 0.f;
#pragma unroll
        for (int q = 0; q < 16; q += 2) {
            float4 xa = xk[q];
            float4 xb = xk[q + 1];
            float4 aL = pL0[0]; float4 aL2 = pL0[1]; pL0 += 2;
            float4 aH = pH0[0]; float4 aH2 = pH0[1]; pH0 += 2;
            float4 bL = pL1[0]; float4 bL2 = pL1[1]; pL1 += 2;
            float4 bH = pH1[0]; float4 bH2 = pH1[1]; pH1 += 2;
            mlA = fmaf(xa.x, aL.x, mlA); mlA = fmaf(xa.y, aL.y, mlA);
            mlA = fmaf(xa.z, aL.z, mlA); mlA = fmaf(xa.w, aL.w, mlA);
            mhA = fmaf(xa.x, aH.x, mhA); mhA = fmaf(xa.y, aH.y, mhA);
            mhA = fmaf(xa.z, aH.z, mhA); mhA = fmaf(xa.w, aH.w, mhA);
            glA = fmaf(xa.x, bL.x, glA); glA = fmaf(xa.y, bL.y, glA);
            glA = fmaf(xa.z, bL.z, glA); glA = fmaf(xa.w, bL.w, glA);
            ghA = fmaf(xa.x, bH.x, ghA); ghA = fmaf(xa.y, bH.y, ghA);
            ghA = fmaf(xa.z, bH.z, ghA); ghA = fmaf(xa.w, bH.w, ghA);
            mlB = fmaf(xb.x, aL2.x, mlB); mlB = fmaf(xb.y, aL2.y, mlB);
            mlB = fmaf(xb.z, aL2.z, mlB); mlB = fmaf(xb.w, aL2.w, mlB);
            mhB = fmaf(xb.x, aH2.x, mhB); mhB = fmaf(xb.y, aH2.y, mhB);
            mhB = fmaf(xb.z, aH2.z, mhB); mhB = fmaf(xb.w, aH2.w, mhB);
            glB = fmaf(xb.x, bL2.x, glB); glB = fmaf(xb.y, bL2.y, glB);
            glB = fmaf(xb.z, bL2.z, glB); glB = fmaf(xb.w, bL2.w, glB);
            ghB = fmaf(xb.x, bH2.x, ghB); ghB = fmaf(xb.y, bH2.y, ghB);
            ghB = fmaf(xb.z, bH2.z, ghB); ghB = fmaf(xb.w, bH2.w, ghB);
        }
        float ml = mlA + mlB, mh = mhA + mhB;
        float gl = glA + glB, gh = ghA + ghB;

        float e0 = __expf(ml), e1 = __expf(mh);
        float s = e0 + e1;
#pragma unroll
        for (int o = 16; o; o >>= 1) s += __shfl_xor_sync(~0u, s, o);
        float inv = 1.0f / s;
        g_Wsk[r0 * 32 + l] = make_float2(e0 * inv, e1 * inv);
        g_G[r0 * 32 + l]   = make_float2(gl + fb[l], gh + fb[l + 32]);
    } else {
        int j0 = (blockIdx.x - 125) * 8 + w;     // [0,2000)
        const float4* xv = (const float4*)&v_emb[j0 * 64];

        float elA = 0.f, ehA = 0.f, alA = 0.f, ahA = 0.f;
        float elB = 0.f, ehB = 0.f, alB = 0.f, ahB = 0.f;
#pragma unroll
        for (int q = 0; q < 16; q += 2) {
            float4 xa = xv[q];
            float4 xb = xv[q + 1];
            float4 aL = pL0[0]; float4 aL2 = pL0[1]; pL0 += 2;
            float4 aH = pH0[0]; float4 aH2 = pH0[1]; pH0 += 2;
            float4 bL = pL1[0]; float4 bL2 = pL1[1]; pL1 += 2;
            float4 bH = pH1[0]; float4 bH2 = pH1[1]; pH1 += 2;
            elA = fmaf(xa.x, aL.x, elA); elA = fmaf(xa.y, aL.y, elA);
            elA = fmaf(xa.z, aL.z, elA); elA = fmaf(xa.w, aL.w, elA);
            ehA = fmaf(xa.x, aH.x, ehA); ehA = fmaf(xa.y, aH.y, ehA);
            ehA = fmaf(xa.z, aH.z, ehA); ehA = fmaf(xa.w, aH.w, ehA);
            alA = fmaf(xa.x, bL.x, alA); alA = fmaf(xa.y, bL.y, alA);
            alA = fmaf(xa.z, bL.z, alA); alA = fmaf(xa.w, bL.w, alA);
            ahA = fmaf(xa.x, bH.x, ahA); ahA = fmaf(xa.y, bH.y, ahA);
            ahA = fmaf(xa.z, bH.z, ahA); ahA = fmaf(xa.w, bH.w, ahA);
            elB = fmaf(xb.x, aL2.x, elB); elB = fmaf(xb.y, aL2.y, elB);
            elB = fmaf(xb.z, aL2.z, elB); elB = fmaf(xb.w, aL2.w, elB);
            ehB = fmaf(xb.x, aH2.x, ehB); ehB = fmaf(xb.y, aH2.y, ehB);
            ehB = fmaf(xb.z, aH2.z, ehB); ehB = fmaf(xb.w, aH2.w, ehB);
            alB = fmaf(xb.x, bL2.x, alB); alB = fmaf(xb.y, bL2.y, alB);
            alB = fmaf(xb.z, bL2.z, alB); alB = fmaf(xb.w, bL2.w, alB);
            ahB = fmaf(xb.x, bH2.x, ahB); ahB = fmaf(xb.y, bH2.y, ahB);
            ahB = fmaf(xb.z, bH2.z, ahB); ahB = fmaf(xb.w, bH2.w, ahB);
        }
        float el = elA + elB, eh = ehA + ehB;
        float al = alA + alB, ah = ahA + ahB;
        g_EA[j0 * 64 + l]      = make_float2(sigmoid_e(el + eb[l]),      tanhf(al + ab[l]));
        g_EA[j0 * 64 + l + 32] = make_float2(sigmoid_e(eh + eb[l + 32]), tanhf(ah + ab[l + 32]));
    }
}

// =====================================================================
// Kernel S: scan. 1 d per warp, 4096 warps, 512 blocks; block = 8 warps
// sharing one batch b. Per 32-step chunk: cooperative smem staging of
// gathered tables (coalesced LDG), then LDS-only inner loop.
// =====================================================================
__global__ __launch_bounds__(256) void k_scan(const float* __restrict__ Mv0)
{
    __shared__ __align__(16) float2 w_s[32][32];    //  8KB  (step, lane) -> (w[l], w[l+32])
    __shared__ __align__(16) float2 ea_s[32][64];   // 16KB  (step, d)    -> (e, a)
    __shared__ __align__(16) float  buf[8][16][36]; // 18KB  deferred read reduction
    __shared__ int idx_s[32];

    int tid = threadIdx.x;
    int w = tid >> 5, l = tid & 31;
    int wg = blockIdx.x * 8 + w;          // 0..4095
    int b  = wg >> 6;                     // same b for all warps in block
    int d  = wg & 63;

    float s0 = Mv0[l * 64 + d];
    float s1 = Mv0[(l + 32) * 64 + d];

    const int* idxp = g_idx + b * TT;
    float* rd = g_read + b * TT * 64 + d;
    float (*mybuf)[36] = buf[w];

    for (int c = 0; c < 6; c++) {
        int t0 = c * 32;
        if (tid < 32) idx_s[tid] = idxp[t0 + tid];
        __syncthreads();   // also protects w_s/ea_s reuse from previous chunk

        // stage w rows: 32 steps x 32 lanes, coalesced (warp = one step)
#pragma unroll
        for (int k = 0; k < 4; k++) {
            int i = tid + k * 256;
            int st = i >> 5, ll = i & 31;
            int p = idx_s[st];
            w_s[st][ll] = g_Wsk[(p & 0xffff) * 32 + ll];
        }
        // stage ea rows: 32 steps x 64 d, coalesced (half-warp per step-half)
#pragma unroll
        for (int k = 0; k < 8; k++) {
            int i = tid + k * 256;
            int st = i >> 6, dd = i & 63;
            int p = idx_s[st];
            ea_s[st][dd] = g_EA[(p >> 16) * 64 + dd];
        }
        __syncthreads();

#pragma unroll
        for (int h = 0; h < 2; h++) {
#pragma unroll
            for (int j = 0; j < 16; j++) {
                int t = h * 16 + j;
                float2 w2 = w_s[t][l];
                float2 ea = ea_s[t][d];
                float r = w2.x * s0 + w2.y * s1;          // read BEFORE update
                s0 = fmaf(w2.x, fmaf(-ea.x, s0, ea.y), s0);
                s1 = fmaf(w2.y, fmaf(-ea.x, s1, ea.y), s1);
                mybuf[j][l] = r;
            }
            __syncwarp();
            if (l < 16) {
                const float4* rowp = (const float4*)&mybuf[l][0];
                float sum = 0.f;
#pragma unroll
                for (int k = 0; k < 8; k++) {
                    float4 v = rowp[k];
                    sum += (v.x + v.y) + (v.z + v.w);
                }
                rd[(t0 + h * 16 + l) * 64] = sum;
            }
            __syncwarp();
        }
    }

    // tail: t = 192..199 (8 steps)
    {
        if (tid < 8) idx_s[tid] = idxp[192 + tid];
        __syncthreads();

        {   // w rows: 8 steps x 32 lanes = 256 entries, one per thread
            int st = tid >> 5, ll = tid & 31;
            int p = idx_s[st];
            w_s[st][ll] = g_Wsk[(p & 0xffff) * 32 + ll];
        }
#pragma unroll
        for (int k = 0; k < 2; k++) {    // ea rows: 8 steps x 64
            int i = tid + k * 256;
            int st = i >> 6, dd = i & 63;
            int p = idx_s[st];
            ea_s[st][dd] = g_EA[(p >> 16) * 64 + dd];
        }
        __syncthreads();

#pragma unroll
        for (int j = 0; j < 8; j++) {
            float2 w2 = w_s[j][l];
            float2 ea = ea_s[j][d];
            float r = w2.x * s0 + w2.y * s1;
            s0 = fmaf(w2.x, fmaf(-ea.x, s0, ea.y), s0);
            s1 = fmaf(w2.y, fmaf(-ea.x, s1, ea.y), s1);
            mybuf[j][l] = r;
        }
        __syncwarp();
        if (l < 8) {
            const float4* rowp = (const float4*)&mybuf[l][0];
            float sum = 0.f;
#pragma unroll
            for (int k = 0; k < 8; k++) {
                float4 v = rowp[k];
                sum += (v.x + v.y) + (v.z + v.w);
            }
            rd[(192 + l) * 64] = sum;
        }
    }
}

// =====================================================================
// Kernel O: p = sigmoid( tanh(read·fW1^T + G[skill]) · pW^T + pb )
// =====================================================================
__global__ __launch_bounds__(256) void k_out(
    const float* __restrict__ fW, const float* __restrict__ pW,
    const float* __restrict__ pb, float* __restrict__ out)
{
    __shared__ __align__(16) float F1[64 * 68];

    int tid = threadIdx.x;
    {
        const float4* src = (const float4*)fW;
#pragma unroll
        for (int k = 0; k < 4; k++) {
            int i = tid + k * 256;
            int o = i >> 4, q4 = i & 15;
            *(float4*)&F1[o * 68 + q4 * 4] = src[o * 32 + q4];
        }
    }
    __syncthreads();

    int w = tid >> 5, l = tid & 31;
    const float4* pL = (const float4*)&F1[l * 68];
    const float4* pH = (const float4*)&F1[(l + 32) * 68];
    float pl = pW[l], ph = pW[l + 32];
    float pbv = pb[0];

    for (int rp = 0; rp < 2; rp++) {
        int row0 = blockIdx.x * 32 + w * 4 + rp * 2;
        int row1 = row0 + 1;
        int b0 = row0 / 199, t0 = row0 - b0 * 199 + 1;
        int b1 = row1 / 199, t1 = row1 - b1 * 199 + 1;
        int i0 = b0 * TT + t0, i1 = b1 * TT + t1;

        const float4* X0 = (const float4*)&g_read[i0 * 64];
        const float4* X1 = (const float4*)&g_read[i1 * 64];

        float a00 = 0.f, a01 = 0.f, a10 = 0.f, a11 = 0.f;
#pragma unroll
        for (int q = 0; q < 16; q++) {
            float4 xa = X0[q];
            float4 xb = X1[q];
            float4 mL = pL[q];
            float4 mH = pH[q];
            a00 = fmaf(xa.x, mL.x, a00); a00 = fmaf(xa.y, mL.y, a00);
            a00 = fmaf(xa.z, mL.z, a00); a00 = fmaf(xa.w, mL.w, a00);
            a01 = fmaf(xa.x, mH.x, a01); a01 = fmaf(xa.y, mH.y, a01);
            a01 = fmaf(xa.z, mH.z, a01); a01 = fmaf(xa.w, mH.w, a01);
            a10 = fmaf(xb.x, mL.x, a10); a10 = fmaf(xb.y, mL.y, a10);
            a10 = fmaf(xb.z, mL.z, a10); a10 = fmaf(xb.w, mL.w, a10);
            a11 = fmaf(xb.x, mH.x, a11); a11 = fmaf(xb.y, mH.y, a11);
            a11 = fmaf(xb.z, mH.z, a11); a11 = fmaf(xb.w, mH.w, a11);
        }

        int sk0 = g_idx[i0] & 0xffff;
        int sk1 = g_idx[i1] & 0xffff;
        float2 G0 = g_G[sk0 * 32 + l];
        float2 G1 = g_G[sk1 * 32 + l];

        float f00 = tanh_a(a00 + G0.x), f01 = tanh_a(a01 + G0.y);
        float f10 = tanh_a(a10 + G1.x), f11 = tanh_a(a11 + G1.y);

        float r0 = f00 * pl + f01 * ph;
        float r1 = f10 * pl + f11 * ph;
#pragma unroll
        for (int o = 16; o; o >>= 1) {
            r0 += __shfl_xor_sync(~0u, r0, o);
            r1 += __shfl_xor_sync(~0u, r1, o);
        }
        if (l == 0) {
            out[row0] = sigmoid_e(r0 + pbv);
            out[row1] = sigmoid_e(r1 + pbv);
        }
    }
}

// =====================================================================
// launch
// =====================================================================
extern "C" void kernel_launch(void* const* d_in, const int* in_sizes, int n_in,
                              void* d_out, int out_size) {
    const int*   skills    = (const int*)d_in[0];
    const int*   responses = (const int*)d_in[1];
    const float* k_emb     = (const float*)d_in[2];
    const float* v_emb     = (const float*)d_in[3];
    const float* Mk        = (const float*)d_in[4];
    const float* Mv0       = (const float*)d_in[5];
    const float* fW        = (const float*)d_in[6];
    const float* fb        = (const float*)d_in[7];
    const float* eW        = (const float*)d_in[8];
    const float* eb        = (const float*)d_in[9];
    const float* aW        = (const float*)d_in[10];
    const float* ab        = (const float*)d_in[11];
    const float* pW        = (const float*)d_in[12];
    const float* pb        = (const float*)d_in[13];
    float* out = (float*)d_out;

    k_pre <<<375, 256>>>(skills, responses, k_emb, v_emb, Mk, fW, fb, eW, eb, aW, ab);
    k_scan<<<512, 256>>>(Mv0);
    k_out <<<398, 256>>>(fW, pW, pb, out);
}

// round 6
// speedup vs baseline: 1.2889x; 1.1433x over previous
#include <cuda_runtime.h>

#define BB 64
#define TT 200
#define NS 1000

// ---------------- device scratch ----------------
__device__ float2 g_Wsk[1000 * 32];   // (w[l], w[l+32]) per skill, softmaxed
__device__ float2 g_EA [2000 * 64];   // (e, a) per x-index, per d
__device__ float2 g_G  [1000 * 32];   // (g[l], g[l+32]) = k·fW2^T + fb
__device__ int    g_idx[BB * TT];     // skill | (x << 16)
__device__ float  g_read[BB * TT * 64];

static __device__ __forceinline__ float tanh_a(float x) {
    float y; asm("tanh.approx.f32 %0, %1;" : "=f"(y) : "f"(x)); return y;
}
static __device__ __forceinline__ float sigmoid_e(float x) {
    return 1.0f / (1.0f + __expf(-x));
}

// =====================================================================
// Kernel P: precompute tables. 1 row per warp. x-row gather hoisted to
// registers BEFORE weight staging so DRAM latency overlaps it.
// =====================================================================
__global__ __launch_bounds__(256) void k_pre(
    const int* __restrict__ skills, const int* __restrict__ responses,
    const float* __restrict__ k_emb, const float* __restrict__ v_emb,
    const float* __restrict__ Mk, const float* __restrict__ fW,
    const float* __restrict__ fb, const float* __restrict__ eW,
    const float* __restrict__ eb, const float* __restrict__ aW,
    const float* __restrict__ ab)
{
    __shared__ __align__(16) float W0[64 * 68];
    __shared__ __align__(16) float W1[64 * 68];

    int tid = threadIdx.x;
    int w = tid >> 5, l = tid & 31;
    bool isA = blockIdx.x < 125;
    int row = isA ? (blockIdx.x * 8 + w) : ((blockIdx.x - 125) * 8 + w);

    // 1) issue per-warp x-row gather FIRST (the long-latency unique load)
    const float4* xp = isA ? (const float4*)&k_emb[row * 64]
                           : (const float4*)&v_emb[row * 64];
    float4 xr[16];
#pragma unroll
    for (int q = 0; q < 16; q++) xr[q] = xp[q];

    // 2) g_idx (cheap)
    int gt = blockIdx.x * 256 + tid;
    if (gt < BB * TT) {
        int s = skills[gt], r = responses[gt];
        int mr = (r > -1) ? r : 0;
        g_idx[gt] = s | ((s + NS * mr) << 16);
    }

    // 3) weight staging
    {
        const float4* s0 = isA ? (const float4*)Mk : (const float4*)eW;
        const float4* s1f = (const float4*)fW;
        const float4* s1a = (const float4*)aW;
        float4 v0[4], v1[4];
#pragma unroll
        for (int k = 0; k < 4; k++) {
            int i = tid + k * 256;
            int o = i >> 4, q4 = i & 15;
            v0[k] = s0[i];
            v1[k] = isA ? s1f[o * 32 + 16 + q4] : s1a[i];
        }
#pragma unroll
        for (int k = 0; k < 4; k++) {
            int i = tid + k * 256;
            int o = i >> 4, q4 = i & 15;
            *(float4*)&W0[o * 68 + q4 * 4] = v0[k];
            *(float4*)&W1[o * 68 + q4 * 4] = v1[k];
        }
    }
    __syncthreads();

    const float4* pL0 = (const float4*)&W0[l * 68];
    const float4* pH0 = (const float4*)&W0[(l + 32) * 68];
    const float4* pL1 = (const float4*)&W1[l * 68];
    const float4* pH1 = (const float4*)&W1[(l + 32) * 68];

    float c0A = 0.f, c1A = 0.f, c2A = 0.f, c3A = 0.f;
    float c0B = 0.f, c1B = 0.f, c2B = 0.f, c3B = 0.f;
#pragma unroll
    for (int q = 0; q < 16; q += 2) {
        float4 xa = xr[q];
        float4 xb = xr[q + 1];
        float4 aL = pL0[q];  float4 aL2 = pL0[q + 1];
        float4 aH = pH0[q];  float4 aH2 = pH0[q + 1];
        float4 bL = pL1[q];  float4 bL2 = pL1[q + 1];
        float4 bH = pH1[q];  float4 bH2 = pH1[q + 1];
        c0A = fmaf(xa.x, aL.x, c0A); c0A = fmaf(xa.y, aL.y, c0A);
        c0A = fmaf(xa.z, aL.z, c0A); c0A = fmaf(xa.w, aL.w, c0A);
        c1A = fmaf(xa.x, aH.x, c1A); c1A = fmaf(xa.y, aH.y, c1A);
        c1A = fmaf(xa.z, aH.z, c1A); c1A = fmaf(xa.w, aH.w, c1A);
        c2A = fmaf(xa.x, bL.x, c2A); c2A = fmaf(xa.y, bL.y, c2A);
        c2A = fmaf(xa.z, bL.z, c2A); c2A = fmaf(xa.w, bL.w, c2A);
        c3A = fmaf(xa.x, bH.x, c3A); c3A = fmaf(xa.y, bH.y, c3A);
        c3A = fmaf(xa.z, bH.z, c3A); c3A = fmaf(xa.w, bH.w, c3A);
        c0B = fmaf(xb.x, aL2.x, c0B); c0B = fmaf(xb.y, aL2.y, c0B);
        c0B = fmaf(xb.z, aL2.z, c0B); c0B = fmaf(xb.w, aL2.w, c0B);
        c1B = fmaf(xb.x, aH2.x, c1B); c1B = fmaf(xb.y, aH2.y, c1B);
        c1B = fmaf(xb.z, aH2.z, c1B); c1B = fmaf(xb.w, aH2.w, c1B);
        c2B = fmaf(xb.x, bL2.x, c2B); c2B = fmaf(xb.y, bL2.y, c2B);
        c2B = fmaf(xb.z, bL2.z, c2B); c2B = fmaf(xb.w, bL2.w, c2B);
        c3B = fmaf(xb.x, bH2.x, c3B); c3B = fmaf(xb.y, bH2.y, c3B);
        c3B = fmaf(xb.z, bH2.z, c3B); c3B = fmaf(xb.w, bH2.w, c3B);
    }
    float c0 = c0A + c0B, c1 = c1A + c1B;
    float c2 = c2A + c2B, c3 = c3A + c3B;

    if (isA) {
        // softmax (logits tiny; max-subtraction unnecessary)
        float e0 = __expf(c0), e1 = __expf(c1);
        float s = e0 + e1;
#pragma unroll
        for (int o = 16; o; o >>= 1) s += __shfl_xor_sync(~0u, s, o);
        float inv = 1.0f / s;
        g_Wsk[row * 32 + l] = make_float2(e0 * inv, e1 * inv);
        g_G[row * 32 + l]   = make_float2(c2 + fb[l], c3 + fb[l + 32]);
    } else {
        g_EA[row * 64 + l]      = make_float2(sigmoid_e(c0 + eb[l]),      tanhf(c2 + ab[l]));
        g_EA[row * 64 + l + 32] = make_float2(sigmoid_e(c1 + eb[l + 32]), tanhf(c3 + ab[l + 32]));
    }
}

// =====================================================================
// Kernel S: scan. 4096 warps (warp = (b,d)); block = 8 warps, same b,
// d = 8*(blockIdx&7) + w. Register-pipelined double-buffered staging:
// LDG next chunk -> regs, compute current chunk (LDS only), STS regs,
// one __syncthreads per chunk. ea staged only for the block's 8 d's.
// =====================================================================
__global__ __launch_bounds__(256) void k_scan(const float* __restrict__ Mv0)
{
    __shared__ __align__(16) float2 w_s[2][32][32];   // 16KB
    __shared__ __align__(16) float2 ea_s[2][32][8];   //  4KB
    __shared__ __align__(16) float  buf[8][16][36];   // 18KB

    int tid = threadIdx.x;
    int w = tid >> 5, l = tid & 31;
    int b = blockIdx.x >> 3;
    int dbase = (blockIdx.x & 7) << 3;
    int d = dbase + w;

    float s0 = Mv0[l * 64 + d];
    float s1 = Mv0[(l + 32) * 64 + d];

    const int* idxp = g_idx + b * TT;
    float* rd = g_read + b * TT * 64 + d;
    float (*mybuf)[36] = buf[w];

    int est = tid >> 3, edl = tid & 7;   // ea staging coords

    float2 wv[4], eav;
    // ---- load + store chunk 0 into buffer 0
#pragma unroll
    for (int k = 0; k < 4; k++) {
        int p = idxp[w + 8 * k];
        wv[k] = g_Wsk[(p & 0xffff) * 32 + l];
    }
    {
        int pe = idxp[est];
        eav = g_EA[(pe >> 16) * 64 + dbase + edl];
    }
#pragma unroll
    for (int k = 0; k < 4; k++) w_s[0][w + 8 * k][l] = wv[k];
    ea_s[0][est][edl] = eav;
    __syncthreads();

    for (int c = 0; c < 6; c++) {
        int cur = c & 1;
        // ---- issue loads for chunk c+1 (chunk 6 = 8-step tail, clamped)
        if (c < 5) {
            int t0n = (c + 1) * 32;
#pragma unroll
            for (int k = 0; k < 4; k++) {
                int p = idxp[t0n + w + 8 * k];
                wv[k] = g_Wsk[(p & 0xffff) * 32 + l];
            }
            int pe = idxp[t0n + est];
            eav = g_EA[(pe >> 16) * 64 + dbase + edl];
        } else {
#pragma unroll
            for (int k = 0; k < 4; k++) {
                int st = w + 8 * k; st = st < 8 ? st : 7;
                int p = idxp[192 + st];
                wv[k] = g_Wsk[(p & 0xffff) * 32 + l];
            }
            int st2 = est < 8 ? est : 7;
            int pe = idxp[192 + st2];
            eav = g_EA[(pe >> 16) * 64 + dbase + edl];
        }

        // ---- compute chunk c from buffer cur (LDS-only inner loop)
        int t0 = c * 32;
#pragma unroll
        for (int h = 0; h < 2; h++) {
#pragma unroll
            for (int j = 0; j < 16; j++) {
                int t = h * 16 + j;
                float2 w2 = w_s[cur][t][l];
                float2 ea = ea_s[cur][t][w];
                float r = w2.x * s0 + w2.y * s1;          // read BEFORE update
                s0 = fmaf(w2.x, fmaf(-ea.x, s0, ea.y), s0);
                s1 = fmaf(w2.y, fmaf(-ea.x, s1, ea.y), s1);
                mybuf[j][l] = r;
            }
            __syncwarp();
            if (l < 16) {
                const float4* rowp = (const float4*)&mybuf[l][0];
                float sum = 0.f;
#pragma unroll
                for (int k = 0; k < 8; k++) {
                    float4 v = rowp[k];
                    sum += (v.x + v.y) + (v.z + v.w);
                }
                rd[(t0 + h * 16 + l) * 64] = sum;
            }
            __syncwarp();
        }

        // ---- store staged regs into the other buffer
        int nb = cur ^ 1;
#pragma unroll
        for (int k = 0; k < 4; k++) w_s[nb][w + 8 * k][l] = wv[k];
        ea_s[nb][est][edl] = eav;
        __syncthreads();
    }

    // ---- tail: 8 steps from buffer 0
    {
#pragma unroll
        for (int j = 0; j < 8; j++) {
            float2 w2 = w_s[0][j][l];
            float2 ea = ea_s[0][j][w];
            float r = w2.x * s0 + w2.y * s1;
            s0 = fmaf(w2.x, fmaf(-ea.x, s0, ea.y), s0);
            s1 = fmaf(w2.y, fmaf(-ea.x, s1, ea.y), s1);
            mybuf[j][l] = r;
        }
        __syncwarp();
        if (l < 8) {
            const float4* rowp = (const float4*)&mybuf[l][0];
            float sum = 0.f;
#pragma unroll
            for (int k = 0; k < 8; k++) {
                float4 v = rowp[k];
                sum += (v.x + v.y) + (v.z + v.w);
            }
            rd[(192 + l) * 64] = sum;
        }
    }
}

// =====================================================================
// Kernel O: p = sigmoid( tanh(read·fW1^T + G[skill]) · pW^T + pb )
// =====================================================================
__global__ __launch_bounds__(256) void k_out(
    const float* __restrict__ fW, const float* __restrict__ pW,
    const float* __restrict__ pb, float* __restrict__ out)
{
    __shared__ __align__(16) float F1[64 * 68];

    int tid = threadIdx.x;
    {
        const float4* src = (const float4*)fW;
#pragma unroll
        for (int k = 0; k < 4; k++) {
            int i = tid + k * 256;
            int o = i >> 4, q4 = i & 15;
            *(float4*)&F1[o * 68 + q4 * 4] = src[o * 32 + q4];
        }
    }
    __syncthreads();

    int w = tid >> 5, l = tid & 31;
    const float4* pL = (const float4*)&F1[l * 68];
    const float4* pH = (const float4*)&F1[(l + 32) * 68];
    float pl = pW[l], ph = pW[l + 32];
    float pbv = pb[0];

    for (int rp = 0; rp < 2; rp++) {
        int row0 = blockIdx.x * 32 + w * 4 + rp * 2;
        int row1 = row0 + 1;
        int b0 = row0 / 199, t0 = row0 - b0 * 199 + 1;
        int b1 = row1 / 199, t1 = row1 - b1 * 199 + 1;
        int i0 = b0 * TT + t0, i1 = b1 * TT + t1;

        const float4* X0 = (const float4*)&g_read[i0 * 64];
        const float4* X1 = (const float4*)&g_read[i1 * 64];

        float a00 = 0.f, a01 = 0.f, a10 = 0.f, a11 = 0.f;
#pragma unroll
        for (int q = 0; q < 16; q++) {
            float4 xa = X0[q];
            float4 xb = X1[q];
            float4 mL = pL[q];
            float4 mH = pH[q];
            a00 = fmaf(xa.x, mL.x, a00); a00 = fmaf(xa.y, mL.y, a00);
            a00 = fmaf(xa.z, mL.z, a00); a00 = fmaf(xa.w, mL.w, a00);
            a01 = fmaf(xa.x, mH.x, a01); a01 = fmaf(xa.y, mH.y, a01);
            a01 = fmaf(xa.z, mH.z, a01); a01 = fmaf(xa.w, mH.w, a01);
            a10 = fmaf(xb.x, mL.x, a10); a10 = fmaf(xb.y, mL.y, a10);
            a10 = fmaf(xb.z, mL.z, a10); a10 = fmaf(xb.w, mL.w, a10);
            a11 = fmaf(xb.x, mH.x, a11); a11 = fmaf(xb.y, mH.y, a11);
            a11 = fmaf(xb.z, mH.z, a11); a11 = fmaf(xb.w, mH.w, a11);
        }

        int sk0 = g_idx[i0] & 0xffff;
        int sk1 = g_idx[i1] & 0xffff;
        float2 G0 = g_G[sk0 * 32 + l];
        float2 G1 = g_G[sk1 * 32 + l];

        float f00 = tanh_a(a00 + G0.x), f01 = tanh_a(a01 + G0.y);
        float f10 = tanh_a(a10 + G1.x), f11 = tanh_a(a11 + G1.y);

        float r0 = f00 * pl + f01 * ph;
        float r1 = f10 * pl + f11 * ph;
#pragma unroll
        for (int o = 16; o; o >>= 1) {
            r0 += __shfl_xor_sync(~0u, r0, o);
            r1 += __shfl_xor_sync(~0u, r1, o);
        }
        if (l == 0) {
            out[row0] = sigmoid_e(r0 + pbv);
            out[row1] = sigmoid_e(r1 + pbv);
        }
    }
}

// =====================================================================
// launch
// =====================================================================
extern "C" void kernel_launch(void* const* d_in, const int* in_sizes, int n_in,
                              void* d_out, int out_size) {
    const int*   skills    = (const int*)d_in[0];
    const int*   responses = (const int*)d_in[1];
    const float* k_emb     = (const float*)d_in[2];
    const float* v_emb     = (const float*)d_in[3];
    const float* Mk        = (const float*)d_in[4];
    const float* Mv0       = (const float*)d_in[5];
    const float* fW        = (const float*)d_in[6];
    const float* fb        = (const float*)d_in[7];
    const float* eW        = (const float*)d_in[8];
    const float* eb        = (const float*)d_in[9];
    const float* aW        = (const float*)d_in[10];
    const float* ab        = (const float*)d_in[11];
    const float* pW        = (const float*)d_in[12];
    const float* pb        = (const float*)d_in[13];
    float* out = (float*)d_out;

    k_pre <<<375, 256>>>(skills, responses, k_emb, v_emb, Mk, fW, fb, eW, eb, aW, ab);
    k_scan<<<512, 256>>>(Mv0);
    k_out <<<398, 256>>>(fW, pW, pb, out);
}